// round 15
// baseline (speedup 1.0000x reference)
#include <cuda_runtime.h>
#include <cuda_fp16.h>

#define MAX_NODES 100000

// fp16 node features: x[n] as 8 halves = 16B -> ONE gather per endpoint.
__device__ __align__(16) uint4 g_xh[MAX_NODES];

// Folded weights (f32 staging; W2g/W3g pre-rounded to fp16 values):
//   [  0.. 15]  b1[16]
//   [ 16..335]  W1[20][16]
//   [336..591]  W2g[16][16] = fp16_round(diag(g1) @ W2)
//   [592..607]  cs2[16]     = colsum(W2g_rounded)
//   [608..623]  b2f[16]     = b2 + be1 @ W2
//   [624..687]  W3g[16][4]  = fp16_round(diag(g2) @ W3)
//   [688..691]  cs3[4]      = colsum(W3g_rounded)
//   [692..695]  b3f[4]      = b3 + be2 @ W3
__device__ __align__(16) float g_fold[696];
__constant__ __align__(16) float c_fold[696];

__device__ __forceinline__ unsigned hpack(float a, float b) {
    __half2 h = __floats2half2_rn(a, b);
    return *(unsigned*)&h;
}
__device__ __forceinline__ unsigned smem_u32(const void* p) {
    return (unsigned)__cvta_generic_to_shared(p);
}
__device__ __forceinline__ void ldm4(unsigned* r, unsigned addr) {
    asm volatile("ldmatrix.sync.aligned.m8n8.x4.shared.b16 {%0,%1,%2,%3}, [%4];"
        : "=r"(r[0]), "=r"(r[1]), "=r"(r[2]), "=r"(r[3]) : "r"(addr) : "memory");
}
__device__ __forceinline__ void mma16816(float* c, const unsigned* a, const unsigned* b) {
    asm volatile("mma.sync.aligned.m16n8k16.row.col.f32.f16.f16.f32 "
        "{%0,%1,%2,%3}, {%4,%5,%6,%7}, {%8,%9}, {%0,%1,%2,%3};"
        : "+f"(c[0]), "+f"(c[1]), "+f"(c[2]), "+f"(c[3])
        : "r"(a[0]), "r"(a[1]), "r"(a[2]), "r"(a[3]), "r"(b[0]), "r"(b[1]));
}
// 4-lane group reduce (lanes sharing l>>2)
__device__ __forceinline__ float grp4(float v) {
    v += __shfl_xor_sync(0xffffffffu, v, 1);
    v += __shfl_xor_sync(0xffffffffu, v, 2);
    return v;
}

__global__ void __launch_bounds__(256)
node_kernel(const float4* __restrict__ x4,
            const float* __restrict__ W1, const float* __restrict__ b1,
            const float* __restrict__ g1, const float* __restrict__ be1,
            const float* __restrict__ W2, const float* __restrict__ b2,
            const float* __restrict__ g2, const float* __restrict__ be2,
            const float* __restrict__ W3, const float* __restrict__ b3,
            int N)
{
    // Block 0 computes the folded-weight block (strided: 320 > blockDim.x).
    if (blockIdx.x == 0) {
        for (int t = threadIdx.x; t < 320; t += blockDim.x) {
            if (t < 16) g_fold[t] = b1[t];
            g_fold[16 + t] = W1[t];
            if (t < 256)
                g_fold[336 + t] = __half2float(__float2half_rn(g1[t >> 4] * W2[t]));
            if (t < 16) {
                float cs = 0.f, bf = b2[t];
                for (int i = 0; i < 16; i++) {
                    cs += __half2float(__float2half_rn(g1[i] * W2[i * 16 + t]));
                    bf += be1[i] * W2[i * 16 + t];
                }
                g_fold[592 + t] = cs;
                g_fold[608 + t] = bf;
            }
            if (t < 64)
                g_fold[624 + t] = __half2float(__float2half_rn(g2[t >> 2] * W3[t]));
            if (t < 4) {
                float cs = 0.f, bf = b3[t];
                for (int i = 0; i < 16; i++) {
                    cs += __half2float(__float2half_rn(g2[i] * W3[i * 4 + t]));
                    bf += be2[i] * W3[i * 4 + t];
                }
                g_fold[688 + t] = cs;
                g_fold[692 + t] = bf;
            }
        }
    }

    int n = blockIdx.x * blockDim.x + threadIdx.x;
    if (n >= N) return;
    float4 x0 = x4[n * 2 + 0];
    float4 x1 = x4[n * 2 + 1];
    uint4 h;
    h.x = hpack(x0.x, x0.y); h.y = hpack(x0.z, x0.w);
    h.z = hpack(x1.x, x1.y); h.w = hpack(x1.z, x1.w);
    g_xh[n] = h;
}

// Warp = 32 edges. A staged in smem (80B row stride, conflict-free),
// all GEMVs as m16n8k16 HMMA; LN via 4-lane shuffles; C->A fragment chaining.
__global__ void __launch_bounds__(128, 6)
edge_kernel(const int* __restrict__ ei, const float4* __restrict__ ea4,
            float* __restrict__ out, int E)
{
    __shared__ __align__(16) unsigned char sA[4][32 * 80];
    int lane = threadIdx.x & 31;
    int w    = threadIdx.x >> 5;
    int cb   = lane & 3;      // column group (l%4)
    int rg   = lane >> 2;     // row within 8 (l/4)

    // ---- B fragments + per-lane epilogue constants (one-time, from const bank) ----
    unsigned B1[2][2][2];
#pragma unroll
    for (int kt = 0; kt < 2; kt++)
#pragma unroll
    for (int nt = 0; nt < 2; nt++) {
        int n = nt * 8 + rg;
        int k0 = kt * 16 + cb * 2;
        float v0 = (k0     < 20) ? c_fold[16 + (k0    ) * 16 + n] : 0.f;
        float v1 = (k0 + 1 < 20) ? c_fold[16 + (k0 + 1) * 16 + n] : 0.f;
        float v2 = (k0 + 8 < 20) ? c_fold[16 + (k0 + 8) * 16 + n] : 0.f;
        float v3 = (k0 + 9 < 20) ? c_fold[16 + (k0 + 9) * 16 + n] : 0.f;
        B1[kt][nt][0] = hpack(v0, v1);
        B1[kt][nt][1] = hpack(v2, v3);
    }
    unsigned B2[2][2];
#pragma unroll
    for (int nt = 0; nt < 2; nt++) {
        int n = nt * 8 + rg;
        int k0 = cb * 2;
        B2[nt][0] = hpack(c_fold[336 + k0 * 16 + n],       c_fold[336 + (k0 + 1) * 16 + n]);
        B2[nt][1] = hpack(c_fold[336 + (k0 + 8) * 16 + n], c_fold[336 + (k0 + 9) * 16 + n]);
    }
    unsigned B3[2];
    {
        int n = rg;
        int k0 = cb * 2;
        float v0 = (n < 4) ? c_fold[624 + (k0    ) * 4 + n] : 0.f;
        float v1 = (n < 4) ? c_fold[624 + (k0 + 1) * 4 + n] : 0.f;
        float v2 = (n < 4) ? c_fold[624 + (k0 + 8) * 4 + n] : 0.f;
        float v3 = (n < 4) ? c_fold[624 + (k0 + 9) * 4 + n] : 0.f;
        B3[0] = hpack(v0, v1);
        B3[1] = hpack(v2, v3);
    }
    float b1c[2][2], cs2c[2][2], b2fc[2][2];
#pragma unroll
    for (int nt = 0; nt < 2; nt++)
#pragma unroll
    for (int j = 0; j < 2; j++) {
        int col = nt * 8 + cb * 2 + j;
        b1c[nt][j]  = c_fold[col];
        cs2c[nt][j] = c_fold[592 + col];
        b2fc[nt][j] = c_fold[608 + col];
    }
    float cs3c[2], b3fc[2];
    {
        int c0 = (cb < 2) ? cb * 2 : 0;   // clamp for inactive lanes
        cs3c[0] = c_fold[688 + c0]; cs3c[1] = c_fold[688 + c0 + 1];
        b3fc[0] = c_fold[692 + c0]; b3fc[1] = c_fold[692 + c0 + 1];
    }

    int edgeBaseW = blockIdx.x * 128 + w * 32;

    // ---- gather this lane's edge; stage one 32-half A row ----
    {
        int e  = edgeBaseW + lane;
        int ec = min(e, E - 1);
        int f = ei[ec], t = ei[E + ec];
        uint4 hf = g_xh[f], ht = g_xh[t];
        float4 ea = ea4[ec];
        uint4 tail;
        tail.x = hpack(ea.x, ea.y);
        tail.y = hpack(ea.z, ea.w);
        tail.z = 0u; tail.w = 0u;
        unsigned char* row = &sA[w][lane * 80];
        *(uint4*)(row +  0) = hf;    // k 0..7   (x[frm])
        *(uint4*)(row + 16) = ht;    // k 8..15  (x[to])
        *(uint4*)(row + 32) = tail;  // k 16..19 (ea) + zeros
        *(uint4*)(row + 48) = make_uint4(0u, 0u, 0u, 0u);
    }
    __syncwarp();

    const unsigned swbase = smem_u32(&sA[w][0]);

#pragma unroll
    for (int mt = 0; mt < 2; mt++) {
        unsigned base = swbase + (mt * 16 + (lane & 15)) * 80 + (lane >> 4) * 16;
        unsigned A0[4], A1[4];
        ldm4(A0, base);        // k 0..15
        ldm4(A1, base + 32);   // k 16..31

        // ---- layer 1 ----
        float C0[4] = {0.f,0.f,0.f,0.f}, C1[4] = {0.f,0.f,0.f,0.f};
        mma16816(C0, A0, B1[0][0]); mma16816(C0, A1, B1[1][0]);
        mma16816(C1, A0, B1[0][1]); mma16816(C1, A1, B1[1][1]);

        C0[0] = fmaxf(C0[0] + b1c[0][0], 0.f);
        C0[1] = fmaxf(C0[1] + b1c[0][1], 0.f);
        C0[2] = fmaxf(C0[2] + b1c[0][0], 0.f);
        C0[3] = fmaxf(C0[3] + b1c[0][1], 0.f);
        C1[0] = fmaxf(C1[0] + b1c[1][0], 0.f);
        C1[1] = fmaxf(C1[1] + b1c[1][1], 0.f);
        C1[2] = fmaxf(C1[2] + b1c[1][0], 0.f);
        C1[3] = fmaxf(C1[3] + b1c[1][1], 0.f);

        float sumA = grp4(C0[0]+C0[1]+C1[0]+C1[1]);
        float sumB = grp4(C0[2]+C0[3]+C1[2]+C1[3]);
        float sqA  = grp4(C0[0]*C0[0]+C0[1]*C0[1]+C1[0]*C1[0]+C1[1]*C1[1]);
        float sqB  = grp4(C0[2]*C0[2]+C0[3]*C0[3]+C1[2]*C1[2]+C1[3]*C1[3]);
        float muA = sumA * 0.0625f, muB = sumB * 0.0625f;
        float s1A = rsqrtf(fmaf(sqA, 0.0625f, -muA * muA) + 1e-5f);
        float s1B = rsqrtf(fmaf(sqB, 0.0625f, -muB * muB) + 1e-5f);
        float k1A = s1A * muA, k1B = s1B * muB;

        // ---- layer 2 (C-frag reused as A-frag) ----
        unsigned A2[4] = { hpack(C0[0],C0[1]), hpack(C0[2],C0[3]),
                           hpack(C1[0],C1[1]), hpack(C1[2],C1[3]) };
        float D0[4] = {0.f,0.f,0.f,0.f}, D1[4] = {0.f,0.f,0.f,0.f};
        mma16816(D0, A2, B2[0]);
        mma16816(D1, A2, B2[1]);

        D0[0] = fmaxf(fmaf(s1A, D0[0], fmaf(-k1A, cs2c[0][0], b2fc[0][0])), 0.f);
        D0[1] = fmaxf(fmaf(s1A, D0[1], fmaf(-k1A, cs2c[0][1], b2fc[0][1])), 0.f);
        D0[2] = fmaxf(fmaf(s1B, D0[2], fmaf(-k1B, cs2c[0][0], b2fc[0][0])), 0.f);
        D0[3] = fmaxf(fmaf(s1B, D0[3], fmaf(-k1B, cs2c[0][1], b2fc[0][1])), 0.f);
        D1[0] = fmaxf(fmaf(s1A, D1[0], fmaf(-k1A, cs2c[1][0], b2fc[1][0])), 0.f);
        D1[1] = fmaxf(fmaf(s1A, D1[1], fmaf(-k1A, cs2c[1][1], b2fc[1][1])), 0.f);
        D1[2] = fmaxf(fmaf(s1B, D1[2], fmaf(-k1B, cs2c[1][0], b2fc[1][0])), 0.f);
        D1[3] = fmaxf(fmaf(s1B, D1[3], fmaf(-k1B, cs2c[1][1], b2fc[1][1])), 0.f);

        float sum2A = grp4(D0[0]+D0[1]+D1[0]+D1[1]);
        float sum2B = grp4(D0[2]+D0[3]+D1[2]+D1[3]);
        float sq2A  = grp4(D0[0]*D0[0]+D0[1]*D0[1]+D1[0]*D1[0]+D1[1]*D1[1]);
        float sq2B  = grp4(D0[2]*D0[2]+D0[3]*D0[3]+D1[2]*D1[2]+D1[3]*D1[3]);
        float mu2A = sum2A * 0.0625f, mu2B = sum2B * 0.0625f;
        float s2A = rsqrtf(fmaf(sq2A, 0.0625f, -mu2A * mu2A) + 1e-5f);
        float s2B = rsqrtf(fmaf(sq2B, 0.0625f, -mu2B * mu2B) + 1e-5f);
        float k2A = s2A * mu2A, k2B = s2B * mu2B;

        // ---- layer 3 ----
        unsigned A3[4] = { hpack(D0[0],D0[1]), hpack(D0[2],D0[3]),
                           hpack(D1[0],D1[1]), hpack(D1[2],D1[3]) };
        float C3[4] = {0.f,0.f,0.f,0.f};
        mma16816(C3, A3, B3);

        // ---- output: lanes cb<2 hold valid cols {0,1} / {2,3} ----
        if (cb < 2) {
            float o0 = fmaf(s2A, C3[0], fmaf(-k2A, cs3c[0], b3fc[0]));
            float o1 = fmaf(s2A, C3[1], fmaf(-k2A, cs3c[1], b3fc[1]));
            float o2 = fmaf(s2B, C3[2], fmaf(-k2B, cs3c[0], b3fc[0]));
            float o3 = fmaf(s2B, C3[3], fmaf(-k2B, cs3c[1], b3fc[1]));
            int eA = edgeBaseW + mt * 16 + rg;
            int eB = eA + 8;
            if (eA < E) *(float2*)(out + eA * 4 + cb * 2) = make_float2(o0, o1);
            if (eB < E) *(float2*)(out + eB * 4 + cb * 2) = make_float2(o2, o3);
        }
    }
}

extern "C" void kernel_launch(void* const* d_in, const int* in_sizes, int n_in,
                              void* d_out, int out_size)
{
    const float* x   = (const float*)d_in[0];
    const int*   ei  = (const int*)d_in[1];     // int32 (JAX x64 disabled)
    const float* ea  = (const float*)d_in[2];
    const float* W1  = (const float*)d_in[3];
    const float* b1  = (const float*)d_in[4];
    const float* g1  = (const float*)d_in[5];
    const float* be1 = (const float*)d_in[6];
    const float* W2  = (const float*)d_in[7];
    const float* b2  = (const float*)d_in[8];
    const float* g2  = (const float*)d_in[9];
    const float* be2 = (const float*)d_in[10];
    const float* W3  = (const float*)d_in[11];
    const float* b3  = (const float*)d_in[12];

    int N = in_sizes[0] / 8;
    if (N > MAX_NODES) N = MAX_NODES;
    int E = in_sizes[1] / 2;

    node_kernel<<<(N + 255) / 256, 256>>>((const float4*)x, W1, b1,
                                          g1, be1, W2, b2, g2, be2, W3, b3, N);

    // Stage folded weights into the constant bank (D2D async: graph-capturable).
    void* gfold_dev = nullptr;
    cudaGetSymbolAddress(&gfold_dev, g_fold);
    cudaMemcpyToSymbolAsync(c_fold, gfold_dev, 696 * sizeof(float), 0,
                            cudaMemcpyDeviceToDevice, 0);

    edge_kernel<<<(E + 127) / 128, 128>>>(ei, (const float4*)ea, (float*)d_out, E);
}